// round 11
// baseline (speedup 1.0000x reference)
#include <cuda_runtime.h>
#include <cstdint>

// Problem constants
#define N_ROWS 8192
#define D_COLS 1024
#define D4     256                      // float4 columns per row
#define NBLK1  256                      // kernel1 blocks (1024 threads each)
#define ITERS  8                        // 8 quads = 32 rows per block
#define NBLK2  16                       // stage-2 blocks (optimal split)

// Scratch: per-block folded column sums [256][1024] floats = 1 MB
__device__ float4 g_partial[NBLK1 * D4];
// stage-2: [16][1024] floats = 64 KB
__device__ float4 g_partial2[NBLK2 * D4];

// Input load with 256B L2 fetch-granularity hint (dense stream, no waste)
__device__ __forceinline__ float4 ldg_256B(const float4* p) {
    float4 v;
    asm("ld.global.nc.L2::256B.v4.f32 {%0,%1,%2,%3}, [%4];"
        : "=f"(v.x), "=f"(v.y), "=f"(v.z), "=f"(v.w) : "l"(p));
    return v;
}

// ---------------------------------------------------------------------------
// Kernel 1: streaming column-sum of (source - target).
// 256 blocks x 1024 threads; static unrolled loop of 8 quad-rows (32 rows).
// Thread t's float4 column group (t%256) is fixed across iterations.
// Exit: 4-way smem fold -> 256 float4 per block (1 MB total scratch).
// ---------------------------------------------------------------------------
__global__ __launch_bounds__(1024)
void mmd_colsum_kernel(const float4* __restrict__ src,
                       const float4* __restrict__ tgt) {
    const int t   = threadIdx.x;               // 0..1023
    const int blk = blockIdx.x;                // 0..255
    const long base = (long)blk * (ITERS * 1024) + t;

    float ax = 0.f, ay = 0.f, az = 0.f, aw = 0.f;

#pragma unroll
    for (int i = 0; i < ITERS; i++) {
        const long off = base + (long)i * 1024;
        float4 s = ldg_256B(&src[off]);
        float4 v = ldg_256B(&tgt[off]);
        ax += s.x - v.x;
        ay += s.y - v.y;
        az += s.z - v.z;
        aw += s.w - v.w;
    }

    __shared__ float4 red[1024];
    float4 acc; acc.x = ax; acc.y = ay; acc.z = az; acc.w = aw;
    red[t] = acc;
    __syncthreads();
    if (t < 256) {
        float4 r1 = red[t + 256];
        float4 r2 = red[t + 512];
        float4 r3 = red[t + 768];
        acc = red[t];
        acc.x += r1.x + r2.x + r3.x;
        acc.y += r1.y + r2.y + r3.y;
        acc.z += r1.z + r2.z + r3.z;
        acc.w += r1.w + r2.w + r3.w;
        g_partial[blk * D4 + t] = acc;         // cached store: stays in L2
    }
}

// ---------------------------------------------------------------------------
// Kernel 2: reduce 256 partial rows -> 16 rows. 16 blocks x 1024 threads;
// thread t covers float4-column t%256 of sub-rows; block b sums partial
// rows [b*16, b*16+16): each of the 4 thread-groups takes 4 rows, then a
// 4-way smem fold. All L2-hot. PDL-gated on kernel1.
// ---------------------------------------------------------------------------
__global__ __launch_bounds__(1024)
void mmd_reduce_kernel() {
    cudaGridDependencySynchronize();           // wait for kernel1 completion
    const int t = threadIdx.x;                 // 0..1023
    const int b = blockIdx.x;                  // 0..15
    const int grp = t >> 8;                    // 0..3 (rows)
    const int col = t & 255;                   // float4 column

    float4 a = {0.f, 0.f, 0.f, 0.f};
#pragma unroll
    for (int r = 0; r < 4; r++) {
        float4 v = g_partial[(long)(b * 16 + grp * 4 + r) * D4 + col];
        a.x += v.x; a.y += v.y; a.z += v.z; a.w += v.w;
    }

    __shared__ float4 red[1024];
    red[t] = a;
    __syncthreads();
    if (t < 256) {
        float4 r1 = red[t + 256];
        float4 r2 = red[t + 512];
        float4 r3 = red[t + 768];
        a = red[t];
        a.x += r1.x + r2.x + r3.x;
        a.y += r1.y + r2.y + r3.y;
        a.z += r1.z + r2.z + r3.z;
        a.w += r1.w + r2.w + r3.w;
        g_partial2[b * D4 + t] = a;
    }
}

// ---------------------------------------------------------------------------
// Kernel 3: finish column sums over 16 rows (64 KB, L2-hot), square,
// reduce, scale, write scalar. 1024 threads: 4 thread-groups x 4 rows each,
// float4 loads, 4-way fold, then scalar tree-reduce. Fixed order. PDL-gated.
// ---------------------------------------------------------------------------
__global__ __launch_bounds__(1024)
void mmd_final_kernel(float* __restrict__ out) {
    cudaGridDependencySynchronize();           // wait for kernel2 completion
    const int t = threadIdx.x;
    const int grp = t >> 8;                    // 0..3
    const int col = t & 255;                   // float4 column

    float4 a = {0.f, 0.f, 0.f, 0.f};
#pragma unroll
    for (int r = 0; r < 4; r++) {
        float4 v = g_partial2[(long)(grp * 4 + r) * D4 + col];
        a.x += v.x; a.y += v.y; a.z += v.z; a.w += v.w;
    }

    __shared__ float4 redv[1024];
    redv[t] = a;
    __syncthreads();

    __shared__ float red[256];
    if (t < 256) {
        float4 r1 = redv[t + 256];
        float4 r2 = redv[t + 512];
        float4 r3 = redv[t + 768];
        a = redv[t];
        a.x += r1.x + r2.x + r3.x;
        a.y += r1.y + r2.y + r3.y;
        a.z += r1.z + r2.z + r3.z;
        a.w += r1.w + r2.w + r3.w;
        // a now holds the 4 final column sums of this column group: square
        red[t] = a.x * a.x + a.y * a.y + a.z * a.z + a.w * a.w;
    }
    __syncthreads();
#pragma unroll
    for (int off = 128; off > 0; off >>= 1) {
        if (t < off) red[t] += red[t + off];
        __syncthreads();
    }
    if (t == 0)
        out[0] = red[0] * (1.0f / ((float)N_ROWS * (float)N_ROWS));
}

// ---------------------------------------------------------------------------
extern "C" void kernel_launch(void* const* d_in, const int* in_sizes, int n_in,
                              void* d_out, int out_size) {
    const float4* src = (const float4*)d_in[0];
    const float4* tgt = (const float4*)d_in[1];
    float* out = (float*)d_out;

    mmd_colsum_kernel<<<NBLK1, 1024>>>(src, tgt);

    // PDL launches: overlap launch/prologue with the predecessor kernel.
    cudaLaunchAttribute attr[1];
    attr[0].id = cudaLaunchAttributeProgrammaticStreamSerialization;
    attr[0].val.programmaticStreamSerializationAllowed = 1;

    {
        cudaLaunchConfig_t cfg = {};
        cfg.gridDim  = dim3(NBLK2, 1, 1);
        cfg.blockDim = dim3(1024, 1, 1);
        cfg.dynamicSmemBytes = 0;
        cfg.stream = 0;
        cfg.attrs = attr;
        cfg.numAttrs = 1;
        cudaLaunchKernelEx(&cfg, mmd_reduce_kernel);
    }
    {
        cudaLaunchConfig_t cfg = {};
        cfg.gridDim  = dim3(1, 1, 1);
        cfg.blockDim = dim3(1024, 1, 1);
        cfg.dynamicSmemBytes = 0;
        cfg.stream = 0;
        cfg.attrs = attr;
        cfg.numAttrs = 1;
        cudaLaunchKernelEx(&cfg, mmd_final_kernel, out);
    }
}